// round 1
// baseline (speedup 1.0000x reference)
#include <cuda_runtime.h>
#include <cstdint>

// Problem constants
#define NROWS 65536   // 64*1024 latent rows
#define DIM   256
#define NE    8192

// Output packing (float32, in reference return order)
#define XQ_OFF   0ULL
#define LOSS_OFF 16777216ULL
#define IDX_OFF  16777217ULL
#define D_OFF    16842753ULL

// Scratch (device globals; no allocation allowed)
__device__ float  g_xnorm[NROWS];
__device__ float  g_enorm[NE];
__device__ int    g_idx[NROWS];
__device__ double g_losssum;

// ---------------------------------------------------------------------------
// Kernel 1: row norms for x and emb, plus zeroing the loss accumulator.
// One warp per row (256 floats -> 8 per lane).
// ---------------------------------------------------------------------------
__global__ void __launch_bounds__(256) vq_norms(const float* __restrict__ x,
                                                const float* __restrict__ emb) {
    if (blockIdx.x == 0 && threadIdx.x == 0) g_losssum = 0.0;
    int warp = threadIdx.x >> 5;
    int lane = threadIdx.x & 31;
    int row = blockIdx.x * 8 + warp;   // rows [0, NE) -> emb, [NE, NE+NROWS) -> x
    const float* src;
    float* dst;
    if (row < NE) {
        src = emb + (size_t)row * DIM;
        dst = g_enorm + row;
    } else {
        int r = row - NE;
        if (r >= NROWS) return;
        src = x + (size_t)r * DIM;
        dst = g_xnorm + r;
    }
    const float4* p = (const float4*)src;
    float4 v0 = p[lane * 2];
    float4 v1 = p[lane * 2 + 1];
    float s = v0.x*v0.x + v0.y*v0.y + v0.z*v0.z + v0.w*v0.w
            + v1.x*v1.x + v1.y*v1.y + v1.z*v1.z + v1.w*v1.w;
    #pragma unroll
    for (int o = 16; o > 0; o >>= 1)
        s += __shfl_down_sync(0xffffffffu, s, o);
    if (lane == 0) *dst = s;
}

// ---------------------------------------------------------------------------
// Kernel 2: main fused kernel.
// Each CTA: 128 rows of x resident in smem (full K=256), loops over all 8192
// codes in 128-wide chunks. Computes d = xn + en - 2*dot, writes d, tracks
// per-row running (min, argmin). 256 threads, 8x8 micro-tile per thread.
// ---------------------------------------------------------------------------
#define BM 128
#define BN 128
#define BK 32
#define APAD 132                        // padded row stride (floats)
#define SMEM_A_FLOATS (DIM * APAD)      // 256*132
#define SMEM_B_FLOATS (BK * APAD)       // 32*132
#define SMEM_BYTES ((SMEM_A_FLOATS + SMEM_B_FLOATS) * 4)

__global__ void __launch_bounds__(256) vq_main(const float* __restrict__ x,
                                               const float* __restrict__ emb,
                                               float* __restrict__ out) {
    extern __shared__ float smem[];
    float* As = smem;                   // [256][132], layout As[k][m]
    float* Bs = smem + SMEM_A_FLOATS;   // [32][132],  layout Bs[k][n]

    const int tid = threadIdx.x;
    const int tx = tid & 15;            // n-dim
    const int ty = tid >> 4;            // m-dim
    const int m0 = blockIdx.x * BM;

    // --- load full A tile (128 rows x 256 k) transposed into smem, once ---
    {
        const float4* xp = (const float4*)x;
        #pragma unroll
        for (int i = 0; i < 32; i++) {
            int s = tid + i * 256;      // 8192 float4 slots
            int row = s >> 6;           // 0..127
            int kv = s & 63;            // float4 index along K
            float4 v = xp[(size_t)(m0 + row) * 64 + kv];
            int kb = kv * 4;
            As[(kb + 0) * APAD + row] = v.x;
            As[(kb + 1) * APAD + row] = v.y;
            As[(kb + 2) * APAD + row] = v.z;
            As[(kb + 3) * APAD + row] = v.w;
        }
    }
    __syncthreads();

    // thread's row set: {4*ty+i} U {64+4*ty+i}
    int rows[8];
    float xn[8];
    #pragma unroll
    for (int i = 0; i < 8; i++) {
        rows[i] = (i < 4) ? (4 * ty + i) : (64 + 4 * ty + (i - 4));
        xn[i] = g_xnorm[m0 + rows[i]];
    }

    float minv[8];
    int mini[8];
    #pragma unroll
    for (int i = 0; i < 8; i++) { minv[i] = 3.4e38f; mini[i] = 0; }

    const float4* ep = (const float4*)emb;

    for (int n0 = 0; n0 < NE; n0 += BN) {
        float acc[8][8];
        #pragma unroll
        for (int i = 0; i < 8; i++)
            #pragma unroll
            for (int j = 0; j < 8; j++) acc[i][j] = 0.0f;

        for (int kt = 0; kt < DIM / BK; kt++) {
            __syncthreads();   // previous compute / prior use of Bs done
            // load B tile: 128 emb rows x 32 k, transposed
            #pragma unroll
            for (int i = 0; i < 4; i++) {
                int s = tid + i * 256;      // 1024 float4 slots
                int row = s >> 3;           // 0..127
                int kv = s & 7;
                float4 v = ep[(size_t)(n0 + row) * 64 + kt * 8 + kv];
                int kb = kv * 4;
                Bs[(kb + 0) * APAD + row] = v.x;
                Bs[(kb + 1) * APAD + row] = v.y;
                Bs[(kb + 2) * APAD + row] = v.z;
                Bs[(kb + 3) * APAD + row] = v.w;
            }
            __syncthreads();

            #pragma unroll 8
            for (int kk = 0; kk < BK; kk++) {
                const float* Ak = As + (kt * BK + kk) * APAD;
                const float* Bk = Bs + kk * APAD;
                float4 a0 = *(const float4*)(Ak + 4 * ty);
                float4 a1 = *(const float4*)(Ak + 64 + 4 * ty);
                float4 b0 = *(const float4*)(Bk + 4 * tx);
                float4 b1 = *(const float4*)(Bk + 64 + 4 * tx);
                float av[8] = {a0.x, a0.y, a0.z, a0.w, a1.x, a1.y, a1.z, a1.w};
                float bv[8] = {b0.x, b0.y, b0.z, b0.w, b1.x, b1.y, b1.z, b1.w};
                #pragma unroll
                for (int i = 0; i < 8; i++)
                    #pragma unroll
                    for (int j = 0; j < 8; j++)
                        acc[i][j] = fmaf(av[i], bv[j], acc[i][j]);
            }
        }

        // epilogue: d values, global write, running argmin
        int cols[8];
        float en[8];
        #pragma unroll
        for (int j = 0; j < 8; j++) {
            cols[j] = (j < 4) ? (4 * tx + j) : (64 + 4 * tx + (j - 4));
            en[j] = g_enorm[n0 + cols[j]];
        }
        #pragma unroll
        for (int i = 0; i < 8; i++) {
            float* drow = out + D_OFF + (size_t)(m0 + rows[i]) * NE + n0;
            #pragma unroll
            for (int j = 0; j < 8; j++) {   // cols ascending within thread
                float dv = xn[i] + en[j] - 2.0f * acc[i][j];
                drow[cols[j]] = dv;
                if (dv < minv[i]) { minv[i] = dv; mini[i] = n0 + cols[j]; }
            }
        }
    }

    // cross-thread argmin reduction (16 tx candidates per row)
    __syncthreads();
    float* redv = Bs;                       // 128*16 floats = 8KB
    int* redi = (int*)(Bs + 2048);          // 128*16 ints   = 8KB
    #pragma unroll
    for (int i = 0; i < 8; i++) {
        redv[rows[i] * 16 + tx] = minv[i];
        redi[rows[i] * 16 + tx] = mini[i];
    }
    __syncthreads();
    if (tid < BM) {
        int m = tid;
        float bv = redv[m * 16];
        int bi = redi[m * 16];
        #pragma unroll
        for (int t = 1; t < 16; t++) {
            float v = redv[m * 16 + t];
            int ix = redi[m * 16 + t];
            if (v < bv || (v == bv && ix < bi)) { bv = v; bi = ix; }
        }
        g_idx[m0 + m] = bi;
        out[IDX_OFF + m0 + m] = (float)bi;
    }
}

// ---------------------------------------------------------------------------
// Kernel 3: gather x_q, write x_q_ste = x + (x_q - x) (exact reference math),
// accumulate sum((x_q - x)^2) in double.
// ---------------------------------------------------------------------------
__global__ void __launch_bounds__(256) vq_gather(const float* __restrict__ x,
                                                 const float* __restrict__ emb,
                                                 float* __restrict__ out) {
    __shared__ double sd[8];
    int warp = threadIdx.x >> 5;
    int lane = threadIdx.x & 31;
    int row = blockIdx.x * 8 + warp;
    int idx = g_idx[row];
    const float4* e = (const float4*)(emb + (size_t)idx * DIM);
    const float4* xr = (const float4*)(x + (size_t)row * DIM);
    float4* oq = (float4*)(out + XQ_OFF + (size_t)row * DIM);

    float s = 0.0f;
    #pragma unroll
    for (int t = 0; t < 2; t++) {
        int q = lane * 2 + t;
        float4 ev = e[q];
        float4 xv = xr[q];
        float dx = ev.x - xv.x, dy = ev.y - xv.y, dz = ev.z - xv.z, dw = ev.w - xv.w;
        float4 o;
        o.x = xv.x + dx; o.y = xv.y + dy; o.z = xv.z + dz; o.w = xv.w + dw;
        oq[q] = o;
        s += dx*dx + dy*dy + dz*dz + dw*dw;
    }
    #pragma unroll
    for (int o = 16; o > 0; o >>= 1)
        s += __shfl_down_sync(0xffffffffu, s, o);
    if (lane == 0) sd[warp] = (double)s;
    __syncthreads();
    if (threadIdx.x == 0) {
        double bs = 0.0;
        #pragma unroll
        for (int w = 0; w < 8; w++) bs += sd[w];
        atomicAdd(&g_losssum, bs);
    }
}

// ---------------------------------------------------------------------------
// Kernel 4: finalize loss = (1 + BETA) * mean((x_q - x)^2)
// ---------------------------------------------------------------------------
__global__ void vq_loss(float* __restrict__ out) {
    double mse = g_losssum / (double)(NROWS * DIM);
    out[LOSS_OFF] = (float)(1.25 * mse);
}

// ---------------------------------------------------------------------------
extern "C" void kernel_launch(void* const* d_in, const int* in_sizes, int n_in,
                              void* d_out, int out_size) {
    const float* x = (const float*)d_in[0];
    const float* emb = (const float*)d_in[1];
    float* out = (float*)d_out;
    (void)in_sizes; (void)n_in; (void)out_size;

    static bool attr_set = false;
    if (!attr_set) {
        cudaFuncSetAttribute(vq_main, cudaFuncAttributeMaxDynamicSharedMemorySize,
                             SMEM_BYTES);
        attr_set = true;
    }

    vq_norms<<<(NE + NROWS) / 8, 256>>>(x, emb);
    vq_main<<<NROWS / BM, 256, SMEM_BYTES>>>(x, emb, out);
    vq_gather<<<NROWS / 8, 256>>>(x, emb, out);
    vq_loss<<<1, 1>>>(out);
}

// round 5
// speedup vs baseline: 1.8114x; 1.8114x over previous
#include <cuda_runtime.h>
#include <cuda_fp16.h>
#include <cstdint>

// Problem constants
#define NROWS 65536
#define DIM   256
#define NE    8192

// Output packing (float32, reference return order)
#define XQ_OFF   0ULL
#define LOSS_OFF 16777216ULL
#define IDX_OFF  16777217ULL
#define D_OFF    16842753ULL

// ---------------------------------------------------------------------------
// Device scratch
// ---------------------------------------------------------------------------
__device__ uint4 g_xs[NROWS * 64];   // [hi(256)|lo(256)] fp16 per row (64MB)
__device__ uint4 g_es[NE * 64];      // emb split, pre-scaled by 4096 (8MB)
__device__ __align__(16) float g_xnorm[NROWS];
__device__ __align__(16) float g_enorm[NE];
__device__ int    g_cand[NROWS * 16];   // 16 argmin candidates per row (4MB)
__device__ int    g_idx[NROWS];
__device__ double g_losssum;

// ---------------------------------------------------------------------------
// helpers
// ---------------------------------------------------------------------------
__device__ __forceinline__ uint32_t smem_to_u32(const void* p) {
    uint32_t a;
    asm("{ .reg .u64 t; cvta.to.shared.u64 t, %1; cvt.u32.u64 %0, t; }"
        : "=r"(a) : "l"(p));
    return a;
}
__device__ __forceinline__ uint64_t to_global(const void* p) {
    uint64_t g;
    asm("cvta.to.global.u64 %0, %1;" : "=l"(g) : "l"(p));
    return g;
}
#define CP_ASYNC_16(dst, src) \
    asm volatile("cp.async.cg.shared.global [%0], [%1], 16;" :: "r"(dst), "l"(src))
#define CP_COMMIT() asm volatile("cp.async.commit_group;" ::: "memory")
#define CP_WAIT(n)  asm volatile("cp.async.wait_group %0;" :: "n"(n) : "memory")

#define LDMATRIX_X4(r, addr) \
    asm volatile("ldmatrix.sync.aligned.m8n8.x4.shared.b16 {%0,%1,%2,%3}, [%4];" \
        : "=r"((r)[0]), "=r"((r)[1]), "=r"((r)[2]), "=r"((r)[3]) : "r"(addr))

#define MMA_16816(c, a, b0, b1) \
    asm volatile("mma.sync.aligned.m16n8k16.row.col.f32.f16.f16.f32 " \
        "{%0,%1,%2,%3}, {%4,%5,%6,%7}, {%8,%9}, {%0,%1,%2,%3};" \
        : "+f"((c)[0]), "+f"((c)[1]), "+f"((c)[2]), "+f"((c)[3]) \
        : "r"((a)[0]), "r"((a)[1]), "r"((a)[2]), "r"((a)[3]), "r"(b0), "r"(b1))

__device__ __forceinline__ uint32_t pack_half2(__half lo, __half hi) {
    return (uint32_t)__half_as_ushort(lo) | ((uint32_t)__half_as_ushort(hi) << 16);
}

// ---------------------------------------------------------------------------
// prep: fp32 -> [hi|lo] fp16 split rows (emb scaled by 4096)
// ---------------------------------------------------------------------------
__global__ void __launch_bounds__(256) vq_prep(const float* __restrict__ x,
                                               const float* __restrict__ emb) {
    int gid = blockIdx.x * 256 + threadIdx.x;
    const float* src;
    uint4* dstrow;
    float sc;
    int c8;
    if (gid < NROWS * 32) {
        int row = gid >> 5; c8 = gid & 31;
        src = x + (size_t)row * DIM + c8 * 8;
        dstrow = g_xs + (size_t)row * 64; sc = 1.0f;
    } else {
        int g2 = gid - NROWS * 32;
        if (g2 >= NE * 32) return;
        int row = g2 >> 5; c8 = g2 & 31;
        src = emb + (size_t)row * DIM + c8 * 8;
        dstrow = g_es + (size_t)row * 64; sc = 4096.0f;
    }
    float4 v0 = ((const float4*)src)[0];
    float4 v1 = ((const float4*)src)[1];
    float f[8] = {v0.x*sc, v0.y*sc, v0.z*sc, v0.w*sc, v1.x*sc, v1.y*sc, v1.z*sc, v1.w*sc};
    __half h[8], l[8];
    #pragma unroll
    for (int i = 0; i < 8; i++) {
        h[i] = __float2half_rn(f[i]);
        l[i] = __float2half_rn(f[i] - __half2float(h[i]));
    }
    uint4 uh, ul;
    uh.x = pack_half2(h[0], h[1]); uh.y = pack_half2(h[2], h[3]);
    uh.z = pack_half2(h[4], h[5]); uh.w = pack_half2(h[6], h[7]);
    ul.x = pack_half2(l[0], l[1]); ul.y = pack_half2(l[2], l[3]);
    ul.z = pack_half2(l[4], l[5]); ul.w = pack_half2(l[6], l[7]);
    dstrow[c8] = uh;
    dstrow[32 + c8] = ul;
}

// ---------------------------------------------------------------------------
// norms + loss reset
// ---------------------------------------------------------------------------
__global__ void __launch_bounds__(256) vq_norms(const float* __restrict__ x,
                                                const float* __restrict__ emb) {
    if (blockIdx.x == 0 && threadIdx.x == 0) g_losssum = 0.0;
    int warp = threadIdx.x >> 5;
    int lane = threadIdx.x & 31;
    int row = blockIdx.x * 8 + warp;
    const float* src; float* dst;
    if (row < NE) { src = emb + (size_t)row * DIM; dst = g_enorm + row; }
    else {
        int r = row - NE;
        if (r >= NROWS) return;
        src = x + (size_t)r * DIM; dst = g_xnorm + r;
    }
    const float4* p = (const float4*)src;
    float4 v0 = p[lane * 2];
    float4 v1 = p[lane * 2 + 1];
    float s = v0.x*v0.x + v0.y*v0.y + v0.z*v0.z + v0.w*v0.w
            + v1.x*v1.x + v1.y*v1.y + v1.z*v1.z + v1.w*v1.w;
    #pragma unroll
    for (int o = 16; o > 0; o >>= 1)
        s += __shfl_down_sync(0xffffffffu, s, o);
    if (lane == 0) *dst = s;
}

// ---------------------------------------------------------------------------
// Main HMMA kernel: computes+writes d, dumps per-lane top-2 argmin candidates.
// ---------------------------------------------------------------------------
#define BM 128
#define BN 128
#define NCH 12
#define NT  (NE / BN)
#define NQ  (NT * NCH)
#define SM_A 0
#define SM_B 131072
#define SMEM_TOTAL 196608

__global__ void __launch_bounds__(256, 1) vq_main_mma(float* __restrict__ out) {
    extern __shared__ char smem[];
    const uint32_t smem_u32 = smem_to_u32(smem);
    const uint32_t Ab = smem_u32 + SM_A;
    const int tid = threadIdx.x;
    const int lane = tid & 31;
    const int wid = tid >> 5;
    const int wm = wid & 3;
    const int wn = wid >> 2;
    const int g = lane >> 2;
    const int t = lane & 3;
    const int m0 = blockIdx.x * BM;

    const uint64_t xs_g = to_global(g_xs);
    const uint64_t es_g = to_global(g_es);

    // A load
    #pragma unroll
    for (int i = 0; i < 32; i++) {
        int idx = tid + i * 256;
        int row = idx >> 6;
        int ch  = idx & 63;
        uint64_t src = xs_g + (((uint64_t)(m0 + row)) * 64 + ch) * 16;
        uint32_t dst = Ab + row * 1024 + ((ch ^ (row & 7)) << 4);
        CP_ASYNC_16(dst, src);
    }
    CP_COMMIT();

    // B prologue chunks 0..2
    #pragma unroll
    for (int p = 0; p < 3; p++) {
        int cc = p;
        int bcol = (((cc >> 2) == 1) ? 256 : 0) + (cc & 3) * 64;
        uint32_t dstb = smem_u32 + SM_B + (p & 3) * 16384;
        #pragma unroll
        for (int i = 0; i < 4; i++) {
            int idx = tid + i * 256;
            int row = idx >> 3;
            int ch  = idx & 7;
            uint64_t src = es_g + (((uint64_t)row) * 512 + bcol + ch * 8) * 2;
            uint32_t dst = dstb + row * 128 + ((ch ^ (row & 7)) << 4);
            CP_ASYNC_16(dst, src);
        }
        CP_COMMIT();
    }
    CP_WAIT(3);
    __syncthreads();

    float xnv[4];
    #pragma unroll
    for (int ii = 0; ii < 4; ii++)
        xnv[ii] = g_xnorm[m0 + wm * 32 + (ii >> 1) * 16 + (ii & 1) * 8 + g];
    float mv1[4] = {3.4e38f, 3.4e38f, 3.4e38f, 3.4e38f};
    float mv2[4] = {3.4e38f, 3.4e38f, 3.4e38f, 3.4e38f};
    int   mi1[4] = {0, 0, 0, 0};
    int   mi2[4] = {0, 0, 0, 0};

    int q = 0;
    for (int n = 0; n < NT; n++) {
        const int n0 = n * BN;
        float acc[2][8][4];
        #pragma unroll
        for (int i = 0; i < 2; i++)
            #pragma unroll
            for (int j = 0; j < 8; j++)
                #pragma unroll
                for (int r = 0; r < 4; r++) acc[i][j][r] = 0.0f;

        for (int c = 0; c < NCH; c++, q++) {
            CP_WAIT(2);
            __syncthreads();

            int qi = q + 3;
            if (qi < NQ) {
                int nn = qi / NCH, cc = qi % NCH;
                int bcol = (((cc >> 2) == 1) ? 256 : 0) + (cc & 3) * 64;
                uint32_t dstb = smem_u32 + SM_B + (qi & 3) * 16384;
                #pragma unroll
                for (int i = 0; i < 4; i++) {
                    int idx = tid + i * 256;
                    int row = idx >> 3;
                    int ch  = idx & 7;
                    uint64_t src = es_g + (((uint64_t)(nn * BN + row)) * 512 + bcol + ch * 8) * 2;
                    uint32_t dst = dstb + row * 128 + ((ch ^ (row & 7)) << 4);
                    CP_ASYNC_16(dst, src);
                }
                CP_COMMIT();
            }

            const uint32_t Bb = smem_u32 + SM_B + (q & 3) * 16384;
            const int aK = (((c >> 2) == 2) ? 32 : 0) + (c & 3) * 8;
            #pragma unroll
            for (int ks = 0; ks < 4; ks++) {
                uint32_t a[2][4];
                #pragma unroll
                for (int i = 0; i < 2; i++) {
                    int row = wm * 32 + i * 16 + (lane & 15);
                    int ch = aK + ks * 2 + (lane >> 4);
                    LDMATRIX_X4(a[i], Ab + row * 1024 + ((ch ^ (row & 7)) << 4));
                }
                uint32_t b[4][4];
                #pragma unroll
                for (int jj = 0; jj < 4; jj++) {
                    int nloc = wn * 64 + jj * 16 + (lane & 7) + ((lane >> 4) << 3);
                    int ch = ks * 2 + ((lane >> 3) & 1);
                    LDMATRIX_X4(b[jj], Bb + nloc * 128 + ((ch ^ (nloc & 7)) << 4));
                }
                #pragma unroll
                for (int i = 0; i < 2; i++)
                    #pragma unroll
                    for (int j = 0; j < 8; j++)
                        MMA_16816(acc[i][j], a[i], b[j >> 1][(j & 1) * 2],
                                  b[j >> 1][(j & 1) * 2 + 1]);
            }
        }

        // epilogue for tile n: d values + top-2 tracking
        const float* enb = g_enorm + n0 + wn * 64 + 2 * t;
        #pragma unroll
        for (int i = 0; i < 2; i++) {
            #pragma unroll
            for (int p = 0; p < 2; p++) {
                const int ii = i * 2 + p;
                const int grow = m0 + wm * 32 + i * 16 + p * 8 + g;
                const float xnr = xnv[ii];
                float* dbase = out + D_OFF + (size_t)grow * NE + n0 + wn * 64 + 2 * t;
                #pragma unroll
                for (int j = 0; j < 8; j++) {
                    float2 e2 = *(const float2*)(enb + j * 8);
                    float S0 = acc[i][j][p * 2];
                    float S1 = acc[i][j][p * 2 + 1];
                    float d0 = fmaf(S0, -4.8828125e-4f, xnr + e2.x);
                    float d1 = fmaf(S1, -4.8828125e-4f, xnr + e2.y);
                    dbase[j * 8] = d0;
                    dbase[j * 8 + 1] = d1;
                    int cidx = n0 + wn * 64 + j * 8 + 2 * t;
                    if (d0 < mv2[ii]) {
                        if (d0 < mv1[ii]) { mv2[ii]=mv1[ii]; mi2[ii]=mi1[ii];
                                            mv1[ii]=d0; mi1[ii]=cidx; }
                        else { mv2[ii]=d0; mi2[ii]=cidx; }
                    }
                    if (d1 < mv2[ii]) {
                        if (d1 < mv1[ii]) { mv2[ii]=mv1[ii]; mi2[ii]=mi1[ii];
                                            mv1[ii]=d1; mi1[ii]=cidx+1; }
                        else { mv2[ii]=d1; mi2[ii]=cidx+1; }
                    }
                }
            }
        }
    }

    // dump per-lane top-2 candidates (8 lanes per row x 2 = 16 per row)
    #pragma unroll
    for (int ii = 0; ii < 4; ii++) {
        int grow = m0 + wm * 32 + (ii >> 1) * 16 + (ii & 1) * 8 + g;
        int base = grow * 16 + (wn * 4 + t) * 2;
        g_cand[base]     = mi1[ii];
        g_cand[base + 1] = mi2[ii];
    }
}

// ---------------------------------------------------------------------------
// Refinement: exact fp32 re-evaluation of the 16 candidates per row,
// bitwise-matching the proven round-1 arithmetic (sequential fmaf chain,
// dv = fmaf(-2, acc, fadd(xn, en))). 16 threads per row.
// ---------------------------------------------------------------------------
__global__ void __launch_bounds__(256) vq_refine(const float* __restrict__ x,
                                                 const float* __restrict__ emb,
                                                 float* __restrict__ out) {
    __shared__ float xs[16][260];
    const int tid = threadIdx.x;
    const int r = tid >> 4;
    const int c = tid & 15;
    const int rb = blockIdx.x * 16;

    // stage 16 x-rows
    #pragma unroll
    for (int i = 0; i < 4; i++) {
        int s = tid + i * 256;           // 1024 float4 slots
        int rr = s >> 6, qq = s & 63;
        float4 v = ((const float4*)(x + (size_t)(rb + rr) * DIM))[qq];
        xs[rr][qq * 4 + 0] = v.x; xs[rr][qq * 4 + 1] = v.y;
        xs[rr][qq * 4 + 2] = v.z; xs[rr][qq * 4 + 3] = v.w;
    }
    __syncthreads();

    const int row = rb + r;
    const int idx = g_cand[row * 16 + c];
    const float* e = emb + (size_t)idx * DIM;
    float acc = 0.0f;
    #pragma unroll 8
    for (int k = 0; k < DIM; k++)
        acc = __fmaf_rn(xs[r][k], __ldg(e + k), acc);
    float dv = __fmaf_rn(-2.0f, acc, __fadd_rn(g_xnorm[row], g_enorm[idx]));

    // lexicographic (value, index) min over the 16 lanes of this row
    float bv = dv; int bi = idx;
    #pragma unroll
    for (int off = 8; off > 0; off >>= 1) {
        float ov = __shfl_down_sync(0xffffffffu, bv, off, 16);
        int   oi = __shfl_down_sync(0xffffffffu, bi, off, 16);
        if (ov < bv || (ov == bv && oi < bi)) { bv = ov; bi = oi; }
    }
    if (c == 0) {
        g_idx[row] = bi;
        out[IDX_OFF + row] = (float)bi;
    }
}

// ---------------------------------------------------------------------------
// gather + loss
// ---------------------------------------------------------------------------
__global__ void __launch_bounds__(256) vq_gather(const float* __restrict__ x,
                                                 const float* __restrict__ emb,
                                                 float* __restrict__ out) {
    __shared__ double sd[8];
    int warp = threadIdx.x >> 5;
    int lane = threadIdx.x & 31;
    int row = blockIdx.x * 8 + warp;
    int idx = g_idx[row];
    const float4* e = (const float4*)(emb + (size_t)idx * DIM);
    const float4* xr = (const float4*)(x + (size_t)row * DIM);
    float4* oq = (float4*)(out + XQ_OFF + (size_t)row * DIM);

    float s = 0.0f;
    #pragma unroll
    for (int tt = 0; tt < 2; tt++) {
        int qq = lane * 2 + tt;
        float4 ev = e[qq];
        float4 xv = xr[qq];
        float dx = ev.x - xv.x, dy = ev.y - xv.y, dz = ev.z - xv.z, dw = ev.w - xv.w;
        float4 o;
        o.x = xv.x + dx; o.y = xv.y + dy; o.z = xv.z + dz; o.w = xv.w + dw;
        oq[qq] = o;
        s += dx*dx + dy*dy + dz*dz + dw*dw;
    }
    #pragma unroll
    for (int o = 16; o > 0; o >>= 1)
        s += __shfl_down_sync(0xffffffffu, s, o);
    if (lane == 0) sd[warp] = (double)s;
    __syncthreads();
    if (threadIdx.x == 0) {
        double bs = 0.0;
        #pragma unroll
        for (int w = 0; w < 8; w++) bs += sd[w];
        atomicAdd(&g_losssum, bs);
    }
}

__global__ void vq_loss(float* __restrict__ out) {
    double mse = g_losssum / (double)(NROWS * DIM);
    out[LOSS_OFF] = (float)(1.25 * mse);
}

// ---------------------------------------------------------------------------
extern "C" void kernel_launch(void* const* d_in, const int* in_sizes, int n_in,
                              void* d_out, int out_size) {
    const float* x = (const float*)d_in[0];
    const float* emb = (const float*)d_in[1];
    float* out = (float*)d_out;
    (void)in_sizes; (void)n_in; (void)out_size;

    static bool attr_set = false;
    if (!attr_set) {
        cudaFuncSetAttribute(vq_main_mma, cudaFuncAttributeMaxDynamicSharedMemorySize,
                             SMEM_TOTAL);
        attr_set = true;
    }

    vq_prep<<<(NROWS + NE) * 32 / 256, 256>>>(x, emb);
    vq_norms<<<(NE + NROWS) / 8, 256>>>(x, emb);
    vq_main_mma<<<NROWS / BM, 256, SMEM_TOTAL>>>(out);
    vq_refine<<<NROWS / 16, 256>>>(x, emb, out);
    vq_gather<<<NROWS / 8, 256>>>(x, emb, out);
    vq_loss<<<1, 1>>>(out);
}

// round 6
// speedup vs baseline: 3.4997x; 1.9320x over previous
#include <cuda_runtime.h>
#include <cuda_fp16.h>
#include <cstdint>

// Problem constants
#define NROWS 65536
#define DIM   256
#define NE    8192

// Output packing (float32, reference return order)
#define XQ_OFF   0ULL
#define LOSS_OFF 16777216ULL
#define IDX_OFF  16777217ULL
#define D_OFF    16842753ULL

// ---------------------------------------------------------------------------
// Device scratch
// ---------------------------------------------------------------------------
__device__ uint4 g_xh[NROWS * 32];   // fp16 x rows (32MB)
__device__ uint4 g_eh[NE * 32];      // fp16 emb rows, pre-scaled by 4096 (4MB)
__device__ __align__(16) float g_xnorm[NROWS];
__device__ __align__(16) float g_enorm[NE];
__device__ int    g_cand[NROWS * 16];   // 16 argmin candidates per row (4MB)
__device__ int    g_idx[NROWS];
__device__ double g_losssum;

// ---------------------------------------------------------------------------
// helpers
// ---------------------------------------------------------------------------
__device__ __forceinline__ uint32_t smem_to_u32(const void* p) {
    uint32_t a;
    asm("{ .reg .u64 t; cvta.to.shared.u64 t, %1; cvt.u32.u64 %0, t; }"
        : "=r"(a) : "l"(p));
    return a;
}
__device__ __forceinline__ uint64_t to_global(const void* p) {
    uint64_t g;
    asm("cvta.to.global.u64 %0, %1;" : "=l"(g) : "l"(p));
    return g;
}
#define CP_ASYNC_16(dst, src) \
    asm volatile("cp.async.cg.shared.global [%0], [%1], 16;" :: "r"(dst), "l"(src))
#define CP_COMMIT() asm volatile("cp.async.commit_group;" ::: "memory")
#define CP_WAIT(n)  asm volatile("cp.async.wait_group %0;" :: "n"(n) : "memory")

#define LDMATRIX_X4(r, addr) \
    asm volatile("ldmatrix.sync.aligned.m8n8.x4.shared.b16 {%0,%1,%2,%3}, [%4];" \
        : "=r"((r)[0]), "=r"((r)[1]), "=r"((r)[2]), "=r"((r)[3]) : "r"(addr))

#define MMA_16816(c, a, b0, b1) \
    asm volatile("mma.sync.aligned.m16n8k16.row.col.f32.f16.f16.f32 " \
        "{%0,%1,%2,%3}, {%4,%5,%6,%7}, {%8,%9}, {%0,%1,%2,%3};" \
        : "+f"((c)[0]), "+f"((c)[1]), "+f"((c)[2]), "+f"((c)[3]) \
        : "r"((a)[0]), "r"((a)[1]), "r"((a)[2]), "r"((a)[3]), "r"(b0), "r"(b1))

__device__ __forceinline__ uint32_t pack_half2(__half lo, __half hi) {
    return (uint32_t)__half_as_ushort(lo) | ((uint32_t)__half_as_ushort(hi) << 16);
}

// ---------------------------------------------------------------------------
// prep: fp32 -> fp16 (emb scaled by 4096)
// ---------------------------------------------------------------------------
__global__ void __launch_bounds__(256) vq_prep(const float* __restrict__ x,
                                               const float* __restrict__ emb) {
    int gid = blockIdx.x * 256 + threadIdx.x;
    const float* src;
    uint4* dst;
    float sc;
    if (gid < NROWS * 32) {
        src = x + (size_t)gid * 8; dst = g_xh + gid; sc = 1.0f;
    } else {
        int g2 = gid - NROWS * 32;
        if (g2 >= NE * 32) return;
        src = emb + (size_t)g2 * 8; dst = g_eh + g2; sc = 4096.0f;
    }
    float4 v0 = ((const float4*)src)[0];
    float4 v1 = ((const float4*)src)[1];
    __half h[8];
    h[0] = __float2half_rn(v0.x * sc); h[1] = __float2half_rn(v0.y * sc);
    h[2] = __float2half_rn(v0.z * sc); h[3] = __float2half_rn(v0.w * sc);
    h[4] = __float2half_rn(v1.x * sc); h[5] = __float2half_rn(v1.y * sc);
    h[6] = __float2half_rn(v1.z * sc); h[7] = __float2half_rn(v1.w * sc);
    uint4 u;
    u.x = pack_half2(h[0], h[1]); u.y = pack_half2(h[2], h[3]);
    u.z = pack_half2(h[4], h[5]); u.w = pack_half2(h[6], h[7]);
    *dst = u;
}

// ---------------------------------------------------------------------------
// norms + loss reset
// ---------------------------------------------------------------------------
__global__ void __launch_bounds__(256) vq_norms(const float* __restrict__ x,
                                                const float* __restrict__ emb) {
    if (blockIdx.x == 0 && threadIdx.x == 0) g_losssum = 0.0;
    int warp = threadIdx.x >> 5;
    int lane = threadIdx.x & 31;
    int row = blockIdx.x * 8 + warp;
    const float* src; float* dst;
    if (row < NE) { src = emb + (size_t)row * DIM; dst = g_enorm + row; }
    else {
        int r = row - NE;
        if (r >= NROWS) return;
        src = x + (size_t)r * DIM; dst = g_xnorm + r;
    }
    const float4* p = (const float4*)src;
    float4 v0 = p[lane * 2];
    float4 v1 = p[lane * 2 + 1];
    float s = v0.x*v0.x + v0.y*v0.y + v0.z*v0.z + v0.w*v0.w
            + v1.x*v1.x + v1.y*v1.y + v1.z*v1.z + v1.w*v1.w;
    #pragma unroll
    for (int o = 16; o > 0; o >>= 1)
        s += __shfl_down_sync(0xffffffffu, s, o);
    if (lane == 0) *dst = s;
}

// ---------------------------------------------------------------------------
// Main HMMA kernel: K=256 (1-term fp16). Writes d, dumps top-2/lane candidates.
// A resident (128 x 256 fp16, 64KB), B streamed in 128x64 chunks, 3 stages.
// ---------------------------------------------------------------------------
#define BM 128
#define BN 128
#define NCH 4                  // k-chunks per n-tile (4 x 64 = K 256)
#define NT  (NE / BN)          // 64
#define NQ  (NT * NCH)         // 256
#define SM_A 0
#define SM_B 65536
#define SMEM_TOTAL 114688      // 64KB A + 3*16KB B

__global__ void __launch_bounds__(256, 1) vq_main_mma(float* __restrict__ out) {
    extern __shared__ char smem[];
    const uint32_t smem_u32 = smem_to_u32(smem);
    const uint32_t Ab = smem_u32 + SM_A;
    const int tid = threadIdx.x;
    const int lane = tid & 31;
    const int wid = tid >> 5;
    const int wm = wid & 3;
    const int wn = wid >> 2;
    const int g = lane >> 2;
    const int t = lane & 3;
    const int m0 = blockIdx.x * BM;

    const uint64_t xh_g = to_global(g_xh);
    const uint64_t eh_g = to_global(g_eh);

    // A load: 128 rows x 32 16B-chunks
    #pragma unroll
    for (int i = 0; i < 16; i++) {
        int idx = tid + i * 256;
        int row = idx >> 5;
        int ch  = idx & 31;
        uint64_t src = xh_g + (((uint64_t)(m0 + row)) * 32 + ch) * 16;
        uint32_t dst = Ab + row * 512 + ((ch ^ (row & 7)) << 4);
        CP_ASYNC_16(dst, src);
    }
    CP_COMMIT();

    // B prologue: chunks 0,1 into stages 0,1
    #pragma unroll
    for (int p = 0; p < 2; p++) {
        uint32_t dstb = smem_u32 + SM_B + p * 16384;
        #pragma unroll
        for (int i = 0; i < 4; i++) {
            int idx = tid + i * 256;
            int row = idx >> 3;
            int ch  = idx & 7;
            uint64_t src = eh_g + (((uint64_t)row) * 32 + p * 8 + ch) * 16;
            uint32_t dst = dstb + row * 128 + ((ch ^ (row & 7)) << 4);
            CP_ASYNC_16(dst, src);
        }
        CP_COMMIT();
    }

    float xnv[4];
    #pragma unroll
    for (int ii = 0; ii < 4; ii++)
        xnv[ii] = g_xnorm[m0 + wm * 32 + (ii >> 1) * 16 + (ii & 1) * 8 + g];
    float mv1[4] = {3.4e38f, 3.4e38f, 3.4e38f, 3.4e38f};
    float mv2[4] = {3.4e38f, 3.4e38f, 3.4e38f, 3.4e38f};
    int   mi1[4] = {0, 0, 0, 0};
    int   mi2[4] = {0, 0, 0, 0};

    int q = 0;
    for (int n = 0; n < NT; n++) {
        const int n0 = n * BN;
        float acc[2][8][4];
        #pragma unroll
        for (int i = 0; i < 2; i++)
            #pragma unroll
            for (int j = 0; j < 8; j++)
                #pragma unroll
                for (int r = 0; r < 4; r++) acc[i][j][r] = 0.0f;

        #pragma unroll
        for (int c = 0; c < NCH; c++, q++) {
            CP_WAIT(1);               // chunk q resident (in-order completion)
            __syncthreads();

            // issue chunk q+2 into stage (q+2)%3; always commit to keep count
            int qi = q + 2;
            if (qi < NQ) {
                int nn = qi >> 2, cc = qi & 3;
                uint32_t dstb = smem_u32 + SM_B + (qi % 3) * 16384;
                #pragma unroll
                for (int i = 0; i < 4; i++) {
                    int idx = tid + i * 256;
                    int row = idx >> 3;
                    int ch  = idx & 7;
                    uint64_t src = eh_g + (((uint64_t)(nn * BN + row)) * 32 + cc * 8 + ch) * 16;
                    uint32_t dst = dstb + row * 128 + ((ch ^ (row & 7)) << 4);
                    CP_ASYNC_16(dst, src);
                }
            }
            CP_COMMIT();

            const uint32_t Bb = smem_u32 + SM_B + (q % 3) * 16384;
            const int aK = c * 8;
            #pragma unroll
            for (int ks = 0; ks < 4; ks++) {
                uint32_t a[2][4];
                #pragma unroll
                for (int i = 0; i < 2; i++) {
                    int row = wm * 32 + i * 16 + (lane & 15);
                    int ch = aK + ks * 2 + (lane >> 4);
                    LDMATRIX_X4(a[i], Ab + row * 512 + ((ch ^ (row & 7)) << 4));
                }
                uint32_t b[4][4];
                #pragma unroll
                for (int jj = 0; jj < 4; jj++) {
                    int nloc = wn * 64 + jj * 16 + (lane & 7) + ((lane >> 4) << 3);
                    int ch = ks * 2 + ((lane >> 3) & 1);
                    LDMATRIX_X4(b[jj], Bb + nloc * 128 + ((ch ^ (nloc & 7)) << 4));
                }
                #pragma unroll
                for (int i = 0; i < 2; i++)
                    #pragma unroll
                    for (int j = 0; j < 8; j++)
                        MMA_16816(acc[i][j], a[i], b[j >> 1][(j & 1) * 2],
                                  b[j >> 1][(j & 1) * 2 + 1]);
            }
        }

        // epilogue for tile n: d values + top-2 tracking
        const float* enb = g_enorm + n0 + wn * 64 + 2 * t;
        #pragma unroll
        for (int i = 0; i < 2; i++) {
            #pragma unroll
            for (int p = 0; p < 2; p++) {
                const int ii = i * 2 + p;
                const int grow = m0 + wm * 32 + i * 16 + p * 8 + g;
                const float xnr = xnv[ii];
                float* dbase = out + D_OFF + (size_t)grow * NE + n0 + wn * 64 + 2 * t;
                #pragma unroll
                for (int j = 0; j < 8; j++) {
                    float2 e2 = *(const float2*)(enb + j * 8);
                    float S0 = acc[i][j][p * 2];
                    float S1 = acc[i][j][p * 2 + 1];
                    float d0 = fmaf(S0, -4.8828125e-4f, xnr + e2.x);  // -2/4096
                    float d1 = fmaf(S1, -4.8828125e-4f, xnr + e2.y);
                    dbase[j * 8] = d0;
                    dbase[j * 8 + 1] = d1;
                    int cidx = n0 + wn * 64 + j * 8 + 2 * t;
                    if (d0 < mv2[ii]) {
                        if (d0 < mv1[ii]) { mv2[ii]=mv1[ii]; mi2[ii]=mi1[ii];
                                            mv1[ii]=d0; mi1[ii]=cidx; }
                        else { mv2[ii]=d0; mi2[ii]=cidx; }
                    }
                    if (d1 < mv2[ii]) {
                        if (d1 < mv1[ii]) { mv2[ii]=mv1[ii]; mi2[ii]=mi1[ii];
                                            mv1[ii]=d1; mi1[ii]=cidx+1; }
                        else { mv2[ii]=d1; mi2[ii]=cidx+1; }
                    }
                }
            }
        }
    }

    // dump per-lane top-2 candidates (8 lanes per row x 2 = 16 per row)
    #pragma unroll
    for (int ii = 0; ii < 4; ii++) {
        int grow = m0 + wm * 32 + (ii >> 1) * 16 + (ii & 1) * 8 + g;
        int base = grow * 16 + (wn * 4 + t) * 2;
        g_cand[base]     = mi1[ii];
        g_cand[base + 1] = mi2[ii];
    }
}

// ---------------------------------------------------------------------------
// Refinement: exact fp32 re-evaluation of 16 candidates/row.
// One warp per row; 2 lanes per candidate (k-halves), float4 loads.
// ---------------------------------------------------------------------------
__global__ void __launch_bounds__(256) vq_refine(const float* __restrict__ x,
                                                 const float* __restrict__ emb,
                                                 float* __restrict__ out) {
    const int lane = threadIdx.x & 31;
    const int row = blockIdx.x * 8 + (threadIdx.x >> 5);
    const int c = lane >> 1;
    const int h = lane & 1;
    const int idx = g_cand[row * 16 + c];

    const float4* xp = (const float4*)(x + (size_t)row * DIM) + h * 32;
    const float4* ep = (const float4*)(emb + (size_t)idx * DIM) + h * 32;
    float acc = 0.0f;
    #pragma unroll
    for (int i = 0; i < 32; i++) {
        float4 ev = __ldg(ep + i);
        float4 xv = xp[i];
        acc = __fmaf_rn(xv.x, ev.x, acc);
        acc = __fmaf_rn(xv.y, ev.y, acc);
        acc = __fmaf_rn(xv.z, ev.z, acc);
        acc = __fmaf_rn(xv.w, ev.w, acc);
    }
    float total = acc + __shfl_xor_sync(0xffffffffu, acc, 1);
    float dv = __fmaf_rn(-2.0f, total,
                         __fadd_rn(g_xnorm[row], g_enorm[idx]));

    // lexicographic (value, index) min over the warp (lane pairs duplicate)
    float bv = dv; int bi = idx;
    #pragma unroll
    for (int off = 16; off > 0; off >>= 1) {
        float ov = __shfl_xor_sync(0xffffffffu, bv, off);
        int   oi = __shfl_xor_sync(0xffffffffu, bi, off);
        if (ov < bv || (ov == bv && oi < bi)) { bv = ov; bi = oi; }
    }
    if (lane == 0) {
        g_idx[row] = bi;
        out[IDX_OFF + row] = (float)bi;
    }
}

// ---------------------------------------------------------------------------
// gather + loss
// ---------------------------------------------------------------------------
__global__ void __launch_bounds__(256) vq_gather(const float* __restrict__ x,
                                                 const float* __restrict__ emb,
                                                 float* __restrict__ out) {
    __shared__ double sd[8];
    int warp = threadIdx.x >> 5;
    int lane = threadIdx.x & 31;
    int row = blockIdx.x * 8 + warp;
    int idx = g_idx[row];
    const float4* e = (const float4*)(emb + (size_t)idx * DIM);
    const float4* xr = (const float4*)(x + (size_t)row * DIM);
    float4* oq = (float4*)(out + XQ_OFF + (size_t)row * DIM);

    float s = 0.0f;
    #pragma unroll
    for (int tt = 0; tt < 2; tt++) {
        int qq = lane * 2 + tt;
        float4 ev = e[qq];
        float4 xv = xr[qq];
        float dx = ev.x - xv.x, dy = ev.y - xv.y, dz = ev.z - xv.z, dw = ev.w - xv.w;
        float4 o;
        o.x = xv.x + dx; o.y = xv.y + dy; o.z = xv.z + dz; o.w = xv.w + dw;
        oq[qq] = o;
        s += dx*dx + dy*dy + dz*dz + dw*dw;
    }
    #pragma unroll
    for (int o = 16; o > 0; o >>= 1)
        s += __shfl_down_sync(0xffffffffu, s, o);
    if (lane == 0) sd[warp] = (double)s;
    __syncthreads();
    if (threadIdx.x == 0) {
        double bs = 0.0;
        #pragma unroll
        for (int w = 0; w < 8; w++) bs += sd[w];
        atomicAdd(&g_losssum, bs);
    }
}

__global__ void vq_loss(float* __restrict__ out) {
    double mse = g_losssum / (double)(NROWS * DIM);
    out[LOSS_OFF] = (float)(1.25 * mse);
}

// ---------------------------------------------------------------------------
extern "C" void kernel_launch(void* const* d_in, const int* in_sizes, int n_in,
                              void* d_out, int out_size) {
    const float* x = (const float*)d_in[0];
    const float* emb = (const float*)d_in[1];
    float* out = (float*)d_out;
    (void)in_sizes; (void)n_in; (void)out_size;

    static bool attr_set = false;
    if (!attr_set) {
        cudaFuncSetAttribute(vq_main_mma, cudaFuncAttributeMaxDynamicSharedMemorySize,
                             SMEM_TOTAL);
        attr_set = true;
    }

    vq_prep<<<(NROWS + NE) * 32 / 256, 256>>>(x, emb);
    vq_norms<<<(NE + NROWS) / 8, 256>>>(x, emb);
    vq_main_mma<<<NROWS / BM, 256, SMEM_TOTAL>>>(out);
    vq_refine<<<NROWS / 8, 256>>>(x, emb, out);
    vq_gather<<<NROWS / 8, 256>>>(x, emb, out);
    vq_loss<<<1, 1>>>(out);
}